// round 4
// baseline (speedup 1.0000x reference)
#include <cuda_runtime.h>
#include <cuda_fp16.h>
#include <math.h>
#include <stdint.h>

#define Bq 4
#define Sq 2048
#define Eq 1024
#define Hq 8
#define Dq 128
#define BS (Bq*Sq)          /* 8192 tokens */
#define HD (Hq*Dq)          /* 1024 */

// ---------------- scratch (static device globals; no allocation) ----------------
__device__ __align__(16) float g_buf0[BS*HD];   // z (f32, scan input) -> h1 (f32)
__device__ __align__(16) float g_buf1[BS*HD];   // scan states (f32)
__device__ __align__(16) float g_buf2[BS*Eq];   // pre-output (f32)
__device__ __align__(16) float g_v[HD];
__device__ __align__(16) float g_c[Hq];
__device__ __align__(16) float g_scores[BS*Hq];
__device__ __align__(16) __half g_xh[BS*Eq];      // x in half (GEMM-A A-operand)
__device__ __align__(16) __half g_hlnh[BS*HD];    // hln in half (GEMM-B A-operand)
__device__ __align__(16) __half g_h1h[BS*HD];     // scaled h1 in half (GEMM-C A-operand)
__device__ __align__(16) __half g_wezTh[Eq*HD];   // W_ez^T half [HD rows, E cols]
__device__ __align__(16) __half g_w2Th[HD*Eq];    // W2^T half [E rows, HD cols]
__device__ __align__(16) __half g_w1Th[Hq*Dq*Dq]; // per-head W1^T half [D, D]

// ================= helpers =================
__device__ __forceinline__ uint32_t smem_u32(const void* p){
  uint32_t a; asm("{ .reg .u64 t; cvta.to.shared.u64 t, %1; cvt.u32.u64 %0, t; }":"=r"(a):"l"(p)); return a;
}
__device__ __forceinline__ void cpasync16(uint32_t dst, const void* src){
  asm volatile("cp.async.cg.shared.global [%0], [%1], 16;"::"r"(dst),"l"(src):"memory");
}
#define CP_COMMIT() asm volatile("cp.async.commit_group;":::"memory")
#define CP_WAIT1()  asm volatile("cp.async.wait_group 1;":::"memory")

#define LDSM4(r0_,r1_,r2_,r3_,addr) \
  asm volatile("ldmatrix.sync.aligned.m8n8.x4.shared.b16 {%0,%1,%2,%3}, [%4];" \
    : "=r"(r0_),"=r"(r1_),"=r"(r2_),"=r"(r3_) : "r"(addr))

#define MMA16(c_, a_, b0_, b1_) \
  asm volatile("mma.sync.aligned.m16n8k16.row.col.f32.f16.f16.f32 " \
    "{%0,%1,%2,%3}, {%4,%5,%6,%7}, {%8,%9}, {%0,%1,%2,%3};" \
    : "+f"((c_)[0]), "+f"((c_)[1]), "+f"((c_)[2]), "+f"((c_)[3]) \
    : "r"((a_)[0]), "r"((a_)[1]), "r"((a_)[2]), "r"((a_)[3]), "r"(b0_), "r"(b1_))

__device__ __forceinline__ void st_half4(__half* p, float a, float b, float c, float d){
  union { __half2 h2[2]; uint2 u; } pk;
  pk.h2[0] = __floats2half2_rn(a, b);
  pk.h2[1] = __floats2half2_rn(c, d);
  *(uint2*)p = pk.u;
}

// =================== fp16 mma.sync GEMM, cp.async 3-stage pipeline ===================
// C[128,128] CTA tile. A [M,K] row-major half. Bt [N,K] row-major half (pre-transposed).
// epi: 0 = tanh(acc+bias[col]); 1 = gelu_exact(acc+bias[col]);
//      2 = acc + sum_h scores[row,h]*b2[h,col]
// SMEM per stage: A 128 rows x 80B pitch (32 halves data) = 10240B; B same. 3 stages.
#define KC 32
#define SA_BYTES 10240
#define STAGE_BYTES 20480
#define GEMM_SMEM 67584     /* max(3*20480=61440, C staging 128*132*4=67584) */

__global__ void __launch_bounds__(256, 2)
mma_gemm(const __half* __restrict__ A, int lda, int sAz,
         const __half* __restrict__ Bt, int ldb, int sBz,
         float* __restrict__ C, int ldc, int sCz,
         int K,
         const float* __restrict__ bias, int sBiasz, int epi,
         const float* __restrict__ scores, const float* __restrict__ b2)
{
    extern __shared__ char smem[];
    const uint32_t sbase = smem_u32(smem);
    const int tid = threadIdx.x, lane = tid & 31, wid = tid >> 5;
    const int wm = wid >> 2, wn = wid & 3;        // warp grid 2(m) x 4(n): 64x32 per warp
    const int bx = blockIdx.x, by = blockIdx.y, bz = blockIdx.z;

    A  += (size_t)bz * sAz + (size_t)(by * 128) * lda;
    Bt += (size_t)bz * sBz + (size_t)(bx * 128) * ldb;

    // loader mapping: id in [0,512): row = id>>2, unit = id&3 (16B per unit)
    const int lr = tid >> 2, lu = tid & 3;

    // ldmatrix per-lane offsets (pitch 80B rows)
    const int lm = lane >> 3;   // matrix id 0..3
    const int aLaneOff = (wm * 64 + (lm & 1) * 8 + (lane & 7)) * 80 + (lm >> 1) * 16;
    const int bLaneOff = (wn * 32 + (lm >> 1) * 8 + (lane & 7)) * 80 + (lm & 1) * 16;

    float cr[4][4][4];
    #pragma unroll
    for (int i = 0; i < 4; i++)
        #pragma unroll
        for (int j = 0; j < 4; j++)
            #pragma unroll
            for (int k = 0; k < 4; k++) cr[i][j][k] = 0.0f;

    const int nch = K / KC;

    // prologue: stages for chunks 0 and 1
    #pragma unroll
    for (int pc = 0; pc < 2; pc++) {
        const int kt = pc * KC;
        const uint32_t sA = sbase + pc * STAGE_BYTES;
        const uint32_t sB = sA + SA_BYTES;
        const __half* ag = A + (size_t)lr * lda + kt + lu * 8;
        const __half* bg = Bt + (size_t)lr * ldb + kt + lu * 8;
        cpasync16(sA + lr * 80 + lu * 16, ag);
        cpasync16(sA + (lr + 64) * 80 + lu * 16, ag + (size_t)64 * lda);
        cpasync16(sB + lr * 80 + lu * 16, bg);
        cpasync16(sB + (lr + 64) * 80 + lu * 16, bg + (size_t)64 * ldb);
        CP_COMMIT();
    }

    for (int c = 0; c < nch; c++) {
        CP_WAIT1();
        __syncthreads();
        if (c + 2 < nch) {
            const int s = (c + 2) % 3;
            const int kt = (c + 2) * KC;
            const uint32_t sA = sbase + s * STAGE_BYTES;
            const uint32_t sB = sA + SA_BYTES;
            const __half* ag = A + (size_t)lr * lda + kt + lu * 8;
            const __half* bg = Bt + (size_t)lr * ldb + kt + lu * 8;
            cpasync16(sA + lr * 80 + lu * 16, ag);
            cpasync16(sA + (lr + 64) * 80 + lu * 16, ag + (size_t)64 * lda);
            cpasync16(sB + lr * 80 + lu * 16, bg);
            cpasync16(sB + (lr + 64) * 80 + lu * 16, bg + (size_t)64 * ldb);
        }
        CP_COMMIT();

        const uint32_t sA = sbase + (c % 3) * STAGE_BYTES;
        const uint32_t sB = sA + SA_BYTES;
        #pragma unroll
        for (int ks = 0; ks < 2; ks++) {
            uint32_t af[4][4];
            #pragma unroll
            for (int mt = 0; mt < 4; mt++)
                LDSM4(af[mt][0], af[mt][1], af[mt][2], af[mt][3],
                      sA + aLaneOff + mt * 1280 + ks * 32);
            #pragma unroll
            for (int nt2 = 0; nt2 < 2; nt2++) {
                uint32_t bf[4];
                LDSM4(bf[0], bf[1], bf[2], bf[3],
                      sB + bLaneOff + nt2 * 1280 + ks * 32);
                #pragma unroll
                for (int mt = 0; mt < 4; mt++) {
                    MMA16(cr[mt][2 * nt2],     af[mt], bf[0], bf[1]);
                    MMA16(cr[mt][2 * nt2 + 1], af[mt], bf[2], bf[3]);
                }
            }
        }
    }
    __syncthreads();

    // ---- epilogue: frags -> padded SMEM (raw), then coalesced copy + epi ----
    float* smC = (float*)smem;   // stride 132 floats per row
    #pragma unroll
    for (int mt = 0; mt < 4; mt++) {
        int r0 = wm * 64 + mt * 16 + (lane >> 2);
        #pragma unroll
        for (int nt = 0; nt < 4; nt++) {
            int col = wn * 32 + nt * 8 + 2 * (lane & 3);
            smC[r0 * 132 + col]           = cr[mt][nt][0];
            smC[r0 * 132 + col + 1]       = cr[mt][nt][1];
            smC[(r0 + 8) * 132 + col]     = cr[mt][nt][2];
            smC[(r0 + 8) * 132 + col + 1] = cr[mt][nt][3];
        }
    }
    __syncthreads();

    C += (size_t)bz * sCz + (size_t)(by * 128) * ldc + bx * 128;
    const float* biasp = bias ? (bias + (size_t)bz * sBiasz + bx * 128) : nullptr;
    const int colc = lane * 4;
    #pragma unroll
    for (int it = 0; it < 16; it++) {
        int r = it * 8 + wid;
        float4 v = *(const float4*)&smC[r * 132 + colc];
        if (epi == 0) {
            v.x = tanhf(v.x + biasp[colc + 0]);
            v.y = tanhf(v.y + biasp[colc + 1]);
            v.z = tanhf(v.z + biasp[colc + 2]);
            v.w = tanhf(v.w + biasp[colc + 3]);
        } else if (epi == 1) {
            float a0 = v.x + biasp[colc + 0];
            float a1 = v.y + biasp[colc + 1];
            float a2 = v.z + biasp[colc + 2];
            float a3 = v.w + biasp[colc + 3];
            v.x = 0.5f * a0 * (1.0f + erff(a0 * 0.70710678118654752f));
            v.y = 0.5f * a1 * (1.0f + erff(a1 * 0.70710678118654752f));
            v.z = 0.5f * a2 * (1.0f + erff(a2 * 0.70710678118654752f));
            v.w = 0.5f * a3 * (1.0f + erff(a3 * 0.70710678118654752f));
        } else if (epi == 2) {
            int grow = by * 128 + r;
            int gcol = bx * 128 + colc;
            #pragma unroll
            for (int hh = 0; hh < 8; hh++) {
                float sc = scores[grow * 8 + hh];      // warp-uniform broadcast
                const float* bp = b2 + hh * Eq + gcol;
                v.x = fmaf(sc, bp[0], v.x);
                v.y = fmaf(sc, bp[1], v.y);
                v.z = fmaf(sc, bp[2], v.z);
                v.w = fmaf(sc, bp[3], v.w);
            }
        }
        *(float4*)(C + (size_t)r * ldc + colc) = v;
    }
}

// ================= x -> half =================
__global__ void __launch_bounds__(256)
x2h_kernel(const float4* __restrict__ x)
{
    int i = blockIdx.x * 256 + threadIdx.x;     // one float4 each
    float4 v = x[i];
    st_half4(g_xh + (size_t)i * 4, v.x, v.y, v.z, v.w);
}

// ================= weight transpose -> half =================
__global__ void __launch_bounds__(256)
transpose_h_kernel(const float* __restrict__ S, __half* __restrict__ D, int n, int zstride)
{
    __shared__ float t[32][33];
    S += (size_t)blockIdx.z * zstride;
    D += (size_t)blockIdx.z * zstride;
    int x  = blockIdx.x * 32 + threadIdx.x;
    int y0 = blockIdx.y * 32;
    #pragma unroll
    for (int j = 0; j < 32; j += 8)
        t[threadIdx.y + j][threadIdx.x] = S[(size_t)(y0 + threadIdx.y + j) * n + x];
    __syncthreads();
    int x2 = blockIdx.y * 32 + threadIdx.x;
    int y2 = blockIdx.x * 32;
    #pragma unroll
    for (int j = 0; j < 32; j += 8)
        D[(size_t)(y2 + threadIdx.y + j) * n + x2] = __float2half_rn(t[threadIdx.x][threadIdx.y + j]);
}

// ================= sequential MinimalRNN scan: one warp per (b,h), 4-deep prefetch =================
__global__ void __launch_bounds__(32)
scan_kernel(const float* __restrict__ U_h, const float* __restrict__ U_z,
            const float* __restrict__ b_u,
            const float* __restrict__ lns_g, const float* __restrict__ lns_b)
{
    const int h = blockIdx.x, b = blockIdx.y;
    const int lane = threadIdx.x;
    const int d0 = lane * 4;

    float uh[4], uz[4], bu[4], gw[4], gb[4];
    #pragma unroll
    for (int c = 0; c < 4; c++) {
        int d = d0 + c;
        uh[c] = U_h[h * Dq * Dq + d * (Dq + 1)];
        uz[c] = U_z[h * Dq * Dq + d * (Dq + 1)];
        bu[c] = b_u[h * Dq + d];
        gw[c] = lns_g[d];
        gb[c] = lns_b[d];
    }

    float hp[4] = {0.f, 0.f, 0.f, 0.f};
    const int off = ((b * Sq) * Hq + h) * Dq + d0;

    float4 zr[4];
    #pragma unroll
    for (int p = 0; p < 4; p++)
        zr[p] = *(const float4*)(g_buf0 + off + p * HD);

    for (int t = 0; t < Sq; t++) {
        float4 zv = zr[t & 3];
        if (t + 4 < Sq)
            zr[t & 3] = *(const float4*)(g_buf0 + off + (t + 4) * HD);
        float zt[4] = {zv.x, zv.y, zv.z, zv.w};

        float hn[4];
        #pragma unroll
        for (int c = 0; c < 4; c++) {
            float a = fmaf(hp[c], uh[c], fmaf(zt[c], uz[c], bu[c]));
            float u = 1.0f / (1.0f + __expf(-a));
            hn[c] = fmaf(u, hp[c] - zt[c], zt[c]);
        }
        float s = (hn[0] + hn[1]) + (hn[2] + hn[3]);
        float q = fmaf(hn[0], hn[0], fmaf(hn[1], hn[1], fmaf(hn[2], hn[2], hn[3] * hn[3])));
        #pragma unroll
        for (int o = 16; o > 0; o >>= 1) {
            s += __shfl_xor_sync(0xffffffffu, s, o);
            q += __shfl_xor_sync(0xffffffffu, q, o);
        }
        float mean = s * (1.0f / Dq);
        float var  = q * (1.0f / Dq) - mean * mean;
        float r = rsqrtf(var + 1e-5f);
        #pragma unroll
        for (int c = 0; c < 4; c++)
            hp[c] = fmaf((hn[c] - mean) * r, gw[c], gb[c]);

        *(float4*)(g_buf1 + off + t * HD) = make_float4(hp[0], hp[1], hp[2], hp[3]);
    }
}

// ================= shaped + per-head LN -> half (g_hlnh) =================
__global__ void __launch_bounds__(256)
hln_kernel(const float* __restrict__ out_shaper,
           const float* __restrict__ ffg, const float* __restrict__ ffb)
{
    int w    = blockIdx.x * 8 + (threadIdx.x >> 5);
    int lane = threadIdx.x & 31;
    int h    = w & 7;
    int d0   = lane * 4;
    int off  = w * Dq + d0;

    float4 xv = *(const float4*)(g_buf1 + off);
    float xs[4] = {xv.x, xv.y, xv.z, xv.w};
    float sh[4];
    #pragma unroll
    for (int c = 0; c < 4; c++) {
        int d = d0 + c;
        sh[c] = xs[c] * out_shaper[h * Dq * Dq + d * (Dq + 1)];
    }
    float s = (sh[0] + sh[1]) + (sh[2] + sh[3]);
    float q = sh[0]*sh[0] + sh[1]*sh[1] + sh[2]*sh[2] + sh[3]*sh[3];
    #pragma unroll
    for (int o = 16; o > 0; o >>= 1) {
        s += __shfl_xor_sync(0xffffffffu, s, o);
        q += __shfl_xor_sync(0xffffffffu, q, o);
    }
    float mean = s * (1.0f / Dq);
    float var  = q * (1.0f / Dq) - mean * mean;
    float r = rsqrtf(var + 1e-5f);
    float o0 = fmaf((sh[0] - mean) * r, ffg[h * Dq + d0 + 0], ffb[h * Dq + d0 + 0]);
    float o1 = fmaf((sh[1] - mean) * r, ffg[h * Dq + d0 + 1], ffb[h * Dq + d0 + 1]);
    float o2 = fmaf((sh[2] - mean) * r, ffg[h * Dq + d0 + 2], ffb[h * Dq + d0 + 2]);
    float o3 = fmaf((sh[3] - mean) * r, ffg[h * Dq + d0 + 3], ffb[h * Dq + d0 + 3]);
    st_half4(g_hlnh + off, o0, o1, o2, o3);
}

// ================= v[h,d] = W2[h,d,:]·w_att, c[h] = b2[h,:]·w_att =================
__global__ void __launch_bounds__(256)
prep_kernel(const float* __restrict__ W2, const float* __restrict__ b2,
            const float* __restrict__ watt)
{
    int w    = blockIdx.x * 8 + (threadIdx.x >> 5);
    int lane = threadIdx.x & 31;
    const float* rowp;
    if (w < HD)            rowp = W2 + (size_t)w * Eq;
    else if (w < HD + Hq)  rowp = b2 + (size_t)(w - HD) * Eq;
    else return;

    float p = 0.0f;
    for (int e = lane * 4; e < Eq; e += 128) {
        float4 a  = *(const float4*)(rowp + e);
        float4 ww = *(const float4*)(watt + e);
        p += a.x * ww.x + a.y * ww.y + a.z * ww.z + a.w * ww.w;
    }
    #pragma unroll
    for (int o = 16; o > 0; o >>= 1) p += __shfl_xor_sync(0xffffffffu, p, o);
    if (lane == 0) {
        if (w < HD) g_v[w] = p;
        else        g_c[w - HD] = p;
    }
}

// ================= per-token head softmax; scaled h1 -> half (g_h1h) =================
__global__ void __launch_bounds__(256)
att_kernel()
{
    int token = blockIdx.x * 8 + (threadIdx.x >> 5);
    int lane  = threadIdx.x & 31;
    int base  = token * HD;

    float4 xv[8];
    float lg[8];
    #pragma unroll
    for (int hh = 0; hh < 8; hh++) {
        xv[hh] = *(const float4*)(g_buf0 + base + hh * Dq + lane * 4);
        float4 vv = *(const float4*)(g_v + hh * Dq + lane * 4);
        float p = xv[hh].x * vv.x + xv[hh].y * vv.y + xv[hh].z * vv.z + xv[hh].w * vv.w;
        #pragma unroll
        for (int o = 16; o > 0; o >>= 1) p += __shfl_xor_sync(0xffffffffu, p, o);
        lg[hh] = p + g_c[hh];
    }
    float m = lg[0];
    #pragma unroll
    for (int hh = 1; hh < 8; hh++) m = fmaxf(m, lg[hh]);
    float ex[8]; float sum = 0.0f;
    #pragma unroll
    for (int hh = 0; hh < 8; hh++) { ex[hh] = __expf(lg[hh] - m); sum += ex[hh]; }
    float inv = 1.0f / sum;
    #pragma unroll
    for (int hh = 0; hh < 8; hh++) {
        float sc = ex[hh] * inv;
        st_half4(g_h1h + base + hh * Dq + lane * 4,
                 xv[hh].x * sc, xv[hh].y * sc, xv[hh].z * sc, xv[hh].w * sc);
    }
    if (lane < 8) g_scores[token * 8 + lane] = ex[lane] * inv;
}

// ================= final LayerNorm over E -> d_out =================
__global__ void __launch_bounds__(256)
lnout_kernel(float* __restrict__ out, const float* __restrict__ g,
             const float* __restrict__ bb)
{
    int row  = blockIdx.x;
    int tid  = threadIdx.x;
    int base = row * Eq;

    float4 xv = *(const float4*)(g_buf2 + base + tid * 4);
    float s = xv.x + xv.y + xv.z + xv.w;
    float q = xv.x*xv.x + xv.y*xv.y + xv.z*xv.z + xv.w*xv.w;
    #pragma unroll
    for (int o = 16; o > 0; o >>= 1) {
        s += __shfl_xor_sync(0xffffffffu, s, o);
        q += __shfl_xor_sync(0xffffffffu, q, o);
    }
    __shared__ float rs[8], rq[8];
    __shared__ float mv[2];
    int warp = tid >> 5, lane = tid & 31;
    if (lane == 0) { rs[warp] = s; rq[warp] = q; }
    __syncthreads();
    if (tid == 0) {
        float S = 0.f, Q = 0.f;
        #pragma unroll
        for (int i = 0; i < 8; i++) { S += rs[i]; Q += rq[i]; }
        float mean = S * (1.0f / Eq);
        float var  = Q * (1.0f / Eq) - mean * mean;
        mv[0] = mean; mv[1] = rsqrtf(var + 1e-5f);
    }
    __syncthreads();
    float mean = mv[0], r = mv[1];
    float4 ov;
    ov.x = fmaf((xv.x - mean) * r, g[tid*4+0], bb[tid*4+0]);
    ov.y = fmaf((xv.y - mean) * r, g[tid*4+1], bb[tid*4+1]);
    ov.z = fmaf((xv.z - mean) * r, g[tid*4+2], bb[tid*4+2]);
    ov.w = fmaf((xv.w - mean) * r, g[tid*4+3], bb[tid*4+3]);
    *(float4*)(out + base + tid * 4) = ov;
}

// ================= launch =================
extern "C" void kernel_launch(void* const* d_in, const int* in_sizes, int n_in,
                              void* d_out, int out_size)
{
    (void)in_sizes; (void)n_in; (void)out_size;
    const float* x     = (const float*)d_in[0];
    const float* W_ez  = (const float*)d_in[1];
    const float* b_ez  = (const float*)d_in[2];
    const float* U_h   = (const float*)d_in[3];
    const float* U_z   = (const float*)d_in[4];
    const float* b_u   = (const float*)d_in[5];
    const float* osh   = (const float*)d_in[6];
    const float* lns_g = (const float*)d_in[7];
    const float* lns_b = (const float*)d_in[8];
    const float* ffg   = (const float*)d_in[9];
    const float* ffb   = (const float*)d_in[10];
    const float* W1    = (const float*)d_in[11];
    const float* fb1   = (const float*)d_in[12];
    const float* W2    = (const float*)d_in[13];
    const float* fb2   = (const float*)d_in[14];
    const float* watt  = (const float*)d_in[15];
    /* d_in[16] = b_att: softmax shift-invariant */
    const float* lno_g = (const float*)d_in[17];
    const float* lno_b = (const float*)d_in[18];
    float* out = (float*)d_out;

    void *p0, *p2, *ps, *pxh, *phl, *ph1, *pwez, *pw2, *pw1;
    cudaGetSymbolAddress(&p0, g_buf0);
    cudaGetSymbolAddress(&p2, g_buf2);
    cudaGetSymbolAddress(&ps, g_scores);
    cudaGetSymbolAddress(&pxh, g_xh);
    cudaGetSymbolAddress(&phl, g_hlnh);
    cudaGetSymbolAddress(&ph1, g_h1h);
    cudaGetSymbolAddress(&pwez, g_wezTh);
    cudaGetSymbolAddress(&pw2, g_w2Th);
    cudaGetSymbolAddress(&pw1, g_w1Th);
    float*  zb    = (float*)p0;
    float*  pb    = (float*)p2;
    float*  scb   = (float*)ps;
    __half* xh    = (__half*)pxh;
    __half* hlnh  = (__half*)phl;
    __half* h1h   = (__half*)ph1;
    __half* wezTh = (__half*)pwez;
    __half* w2Th  = (__half*)pw2;
    __half* w1Th  = (__half*)pw1;

    cudaFuncSetAttribute(mma_gemm, cudaFuncAttributeMaxDynamicSharedMemorySize, GEMM_SMEM);

    // small precomputes
    prep_kernel<<<129, 256>>>(W2, fb2, watt);
    x2h_kernel<<<BS * Eq / 1024, 256>>>((const float4*)x);
    transpose_h_kernel<<<dim3(32, 32, 1), dim3(32, 8)>>>(W_ez, wezTh, 1024, 0);
    transpose_h_kernel<<<dim3(32, 32, 1), dim3(32, 8)>>>(W2, w2Th, 1024, 0);
    transpose_h_kernel<<<dim3(4, 4, 8),  dim3(32, 8)>>>(W1, w1Th, 128, Dq * Dq);

    // GEMM-A: z = tanh(x @ W_ez + b_ez) -> f32 g_buf0
    mma_gemm<<<dim3(8, 64, 1), 256, GEMM_SMEM>>>(xh, 1024, 0, wezTh, 1024, 0,
                                                 zb, 1024, 0, 1024,
                                                 b_ez, 0, 0, nullptr, nullptr);

    // sequential scan -> g_buf1 (f32)
    scan_kernel<<<dim3(8, 4), 32>>>(U_h, U_z, b_u, lns_g, lns_b);

    // shaped + per-head LN -> half g_hlnh
    hln_kernel<<<8192, 256>>>(osh, ffg, ffb);

    // GEMM-B per head: h1 = gelu(hln @ W1[h] + b1[h]) -> f32 g_buf0
    mma_gemm<<<dim3(1, 64, 8), 256, GEMM_SMEM>>>(hlnh, 1024, 128, w1Th, 128, Dq * Dq,
                                                 zb, 1024, 128, 128,
                                                 fb1, 128, 1, nullptr, nullptr);

    // head softmax; scaled h1 -> half g_h1h, scores -> g_scores
    att_kernel<<<1024, 256>>>();

    // GEMM-C: pre = (s*h1) @ W2 + sum_h s_h*b2[h,:] -> f32 g_buf2
    mma_gemm<<<dim3(8, 64, 1), 256, GEMM_SMEM>>>(h1h, 1024, 0, w2Th, 1024, 0,
                                                 pb, 1024, 0, 1024,
                                                 nullptr, 0, 2, scb, fb2);

    // final LN over E
    lnout_kernel<<<8192, 256>>>(out, lno_g, lno_b);
}